// round 16
// baseline (speedup 1.0000x reference)
#include <cuda_runtime.h>
#include <cuda_fp16.h>
#include <cstdint>
#include <math.h>

#define NUM_EXPERTS 32
#define TOP_K 8
#define HIDDEN 1536
#define INTER 512
#define T_TOT 8192
#define CAP 8192
#define ROWS_TOT (T_TOT * TOP_K)
#define R_TILE 64
#define R_BLOCKS (T_TOT / R_TILE)   // 128

// ---------------- device scratch (zero-initialized at module load) ----------------
__device__ int   g_cnt[NUM_EXPERTS];
__device__ int   g_off[NUM_EXPERTS];
__device__ int   g_done;
__device__ int   g_tok[NUM_EXPERTS * CAP];
__device__ float g_wt [NUM_EXPERTS * CAP];
__device__ int   g_pair[T_TOT * TOP_K];

__device__ __half g_xh[(size_t)T_TOT * HIDDEN];
__device__ __half g_w13h[(size_t)NUM_EXPERTS * 2 * INTER * HIDDEN];
__device__ __half g_w2h[(size_t)NUM_EXPERTS * HIDDEN * INTER];
__device__ __half g_h[(size_t)ROWS_TOT * INTER];
__device__ __half g_y[(size_t)ROWS_TOT * HIDDEN];

// ---------------- helpers ----------------
__device__ __forceinline__ uint32_t smem_u32(const void* p) {
    uint32_t a;
    asm("{ .reg .u64 t; cvta.to.shared.u64 t, %1; cvt.u32.u64 %0, t; }" : "=r"(a) : "l"(p));
    return a;
}
__device__ __forceinline__ void cp16(uint32_t dst, const void* src, int sz) {
    asm volatile("cp.async.cg.shared.global [%0], [%1], 16, %2;"
                 :: "r"(dst), "l"(__cvta_generic_to_global(src)), "r"(sz));
}
#define CP_COMMIT() asm volatile("cp.async.commit_group;")
#define CP_WAIT1()  asm volatile("cp.async.wait_group 1;")

__device__ __forceinline__ void ldm4(uint32_t* r, uint32_t addr) {
    asm volatile("ldmatrix.sync.aligned.m8n8.x4.shared.b16 {%0,%1,%2,%3}, [%4];"
                 : "=r"(r[0]), "=r"(r[1]), "=r"(r[2]), "=r"(r[3]) : "r"(addr));
}
__device__ __forceinline__ void mma16816(float* c, const uint32_t* a, uint32_t b0, uint32_t b1) {
    asm volatile("mma.sync.aligned.m16n8k16.row.col.f32.f16.f16.f32 "
                 "{%0,%1,%2,%3}, {%4,%5,%6,%7}, {%8,%9}, {%0,%1,%2,%3};"
                 : "+f"(c[0]), "+f"(c[1]), "+f"(c[2]), "+f"(c[3])
                 : "r"(a[0]), "r"(a[1]), "r"(a[2]), "r"(a[3]), "r"(b0), "r"(b1));
}

// smem: A tile 256 rows x 64 fp16 (32KB), B tile 128 rows x 64 fp16 (16KB)
// rows are 128B, 16B-chunk XOR swizzle (chunk ^ (row & 7))
#define OFF_A   0
#define OFF_B   32768
#define STAGE_B 49152
#define NST 3
#define SMEM_DYN (NST * STAGE_B)   // 147456 -> 1 CTA/SM (512 thr = 16 warps)

struct LoadCtx {
    const __half *a, *b;
    int asz;     // 16 or 0
    int bact;    // thread participates in B loads (tid < 256)
    uint32_t dstA[4], dstB[4];
};

__device__ __forceinline__ void load_stage(uint32_t sm, int st, int koff, const LoadCtx& c) {
    uint32_t bse = sm + st * STAGE_B;
    #pragma unroll
    for (int j = 0; j < 4; j++)
        cp16(bse + OFF_A + c.dstA[j], c.a + koff + j * 8, c.asz);
    if (c.bact) {
        #pragma unroll
        for (int j = 0; j < 4; j++)
            cp16(bse + OFF_B + c.dstB[j], c.b + koff + j * 8, 16);
    }
}

// one BK=64 stage; warp tile 64x32; acc[4][4][4]
__device__ __forceinline__ void compute_stage(
        uint32_t sbase, int lane,
        const uint32_t arow[4], const uint32_t ar7[4],
        const uint32_t brow[2], const uint32_t br7[2],
        float acc[4][4][4]) {
    const uint32_t asel = lane >> 4;
    const uint32_t bsel = (lane >> 3) & 1;
    #pragma unroll
    for (int kk = 0; kk < 4; kk++) {
        uint32_t a[4][4];
        #pragma unroll
        for (int mi = 0; mi < 4; mi++) {
            uint32_t ch = kk * 2 + asel;
            ldm4(a[mi], sbase + OFF_A + arow[mi] + (((ch ^ ar7[mi]) & 7) << 4));
        }
        uint32_t b[2][4];
        #pragma unroll
        for (int q = 0; q < 2; q++) {
            uint32_t ch = kk * 2 + bsel;
            ldm4(b[q], sbase + OFF_B + brow[q] + (((ch ^ br7[q]) & 7) << 4));
        }
        #pragma unroll
        for (int ni = 0; ni < 4; ni++)
            #pragma unroll
            for (int mi = 0; mi < 4; mi++)
                mma16816(acc[mi][ni], a[mi], b[ni >> 1][2 * (ni & 1)], b[ni >> 1][2 * (ni & 1) + 1]);
    }
}

// ---------------- small kernels ----------------
__global__ void tohalf_kernel(const float* __restrict__ src, __half* __restrict__ dst, size_t n8) {
    size_t i = (size_t)blockIdx.x * blockDim.x + threadIdx.x;
    size_t stride = (size_t)gridDim.x * blockDim.x;
    for (; i < n8; i += stride) {
        float4 v0 = __ldcs(((const float4*)src) + 2 * i);
        float4 v1 = __ldcs(((const float4*)src) + 2 * i + 1);
        uint4 o;
        __half2 h0 = __floats2half2_rn(v0.x, v0.y);
        __half2 h1 = __floats2half2_rn(v0.z, v0.w);
        __half2 h2 = __floats2half2_rn(v1.x, v1.y);
        __half2 h3 = __floats2half2_rn(v1.z, v1.w);
        o.x = *(uint32_t*)&h0; o.y = *(uint32_t*)&h1;
        o.z = *(uint32_t*)&h2; o.w = *(uint32_t*)&h3;
        ((uint4*)dst)[i] = o;
    }
}

// ---------------- router: 64-token tiles, logits + fused top-8 + fused prefix ----------------
#define RXS 65
#define RGS 33
#define RLS 33
#define R_SMEM ((128 * RXS + 128 * RGS) * 4)   // 50176 B
__global__ void __launch_bounds__(256) router_kernel(
        const float* __restrict__ x, const float* __restrict__ gate_w) {
    extern __shared__ float rsm[];
    float* xs = rsm;
    float* gs = rsm + 128 * RXS;
    float* ls = rsm;
    const int tid = threadIdx.x, lane = tid & 31;
    const int t0 = blockIdx.x * R_TILE;
    const int e0 = (tid >> 5) * 4;

    float acc[2][4];
    #pragma unroll
    for (int i = 0; i < 2; i++)
        #pragma unroll
        for (int j = 0; j < 4; j++) acc[i][j] = 0.0f;

    for (int ch = 0; ch < HIDDEN / 128; ch++) {
        __syncthreads();
        for (int i = tid; i < 2048; i += 256) {
            int tok = i >> 5, kq = i & 31;
            float4 v = *(const float4*)&x[(size_t)(t0 + tok) * HIDDEN + ch * 128 + kq * 4];
            xs[(4 * kq + 0) * RXS + tok] = v.x;
            xs[(4 * kq + 1) * RXS + tok] = v.y;
            xs[(4 * kq + 2) * RXS + tok] = v.z;
            xs[(4 * kq + 3) * RXS + tok] = v.w;
        }
        for (int i = tid; i < 1024; i += 256) {
            int e = i >> 5, kq = i & 31;
            float4 v = *(const float4*)&gate_w[(size_t)e * HIDDEN + ch * 128 + kq * 4];
            gs[(4 * kq + 0) * RGS + e] = v.x;
            gs[(4 * kq + 1) * RGS + e] = v.y;
            gs[(4 * kq + 2) * RGS + e] = v.z;
            gs[(4 * kq + 3) * RGS + e] = v.w;
        }
        __syncthreads();
        #pragma unroll 4
        for (int kk = 0; kk < 128; kk++) {
            float gg[4];
            #pragma unroll
            for (int j = 0; j < 4; j++) gg[j] = gs[kk * RGS + e0 + j];
            #pragma unroll
            for (int i = 0; i < 2; i++) {
                float xv = xs[kk * RXS + lane + 32 * i];
                #pragma unroll
                for (int j = 0; j < 4; j++) acc[i][j] = fmaf(xv, gg[j], acc[i][j]);
            }
        }
    }

    __syncthreads();
    #pragma unroll
    for (int i = 0; i < 2; i++)
        #pragma unroll
        for (int j = 0; j < 4; j++)
            ls[(lane + 32 * i) * RLS + e0 + j] = acc[i][j];
    __syncthreads();

    if (tid < R_TILE) {
        const int t = t0 + tid;
        float lg[NUM_EXPERTS];
        #pragma unroll
        for (int i = 0; i < NUM_EXPERTS; i++) lg[i] = ls[tid * RLS + i];
        float mx = -INFINITY;
        #pragma unroll
        for (int i = 0; i < NUM_EXPERTS; i++) mx = fmaxf(mx, lg[i]);
        float pr[NUM_EXPERTS];
        #pragma unroll
        for (int i = 0; i < NUM_EXPERTS; i++) pr[i] = expf(lg[i] - mx);
        int idx[TOP_K]; float w[TOP_K]; float ws = 0.0f;
        unsigned used = 0u;
        #pragma unroll
        for (int k = 0; k < TOP_K; k++) {
            int bi = -1; float bv = -INFINITY;
            #pragma unroll
            for (int i = 0; i < NUM_EXPERTS; i++)
                if (!(used >> i & 1u) && pr[i] > bv) { bv = pr[i]; bi = i; }
            used |= 1u << bi; idx[k] = bi; w[k] = bv; ws += bv;
        }
        float inv = 1.0f / ws;
        #pragma unroll
        for (int k = 0; k < TOP_K; k++) {
            int slot = atomicAdd(&g_cnt[idx[k]], 1);
            g_tok[idx[k] * CAP + slot] = t;
            g_wt [idx[k] * CAP + slot] = w[k] * inv;
            g_pair[t * TOP_K + k] = (idx[k] << 20) | slot;
        }
    }

    __syncthreads();
    if (tid == 0) {
        __threadfence();
        int old = atomicAdd(&g_done, 1);
        if (old == R_BLOCKS - 1) {
            int s = 0;
            for (int e = 0; e < NUM_EXPERTS; e++) { g_off[e] = s; s += g_cnt[e]; }
        }
    }
}

// ---------------- GEMM1 (fp16 HMMA, M=256): gu = X @ W13^T, h = silu(g)*u ----------------
// CTA tile 256x128 (N=128: per-warp 16 g-cols + 16 u-cols interleaved).
__global__ void __launch_bounds__(512, 1) gemm1_kernel() {
    const int e = blockIdx.z;
    const int rows = g_cnt[e];
    const int rt = blockIdx.x;
    if (rt * 256 >= rows) return;
    const int ct = blockIdx.y;      // 0..7
    const int base = g_off[e];

    extern __shared__ char smraw[];
    uint32_t sm = smem_u32(smraw);
    const int tid = threadIdx.x, wid = tid >> 5, lane = tid & 31;
    const int wm = wid >> 2, wn = wid & 3;   // 4 x 4 warp grid

    LoadCtx c;
    {
        int ra = tid >> 1;              // 0..255 (A row)
        int kc0 = (tid & 1) * 4;
        int arow = rt * 256 + ra;
        int v = arow < rows;
        int tok = v ? g_tok[e * CAP + arow] : 0;
        c.a = g_xh + (size_t)tok * HIDDEN + kc0 * 8;
        c.asz = v ? 16 : 0;
        #pragma unroll
        for (int j = 0; j < 4; j++)
            c.dstA[j] = (uint32_t)(ra * 128 + (((kc0 + j) ^ (ra & 7)) << 4));

        c.bact = tid < 256;
        int rb = (tid & 255) >> 1;      // 0..127 (B row)
        // B row rb: warp slice wq = rb>>5, gu half = (rb>>4)&1, col-in-slice = rb&15
        int wq = rb >> 5, gu = (rb >> 4) & 1, cc = rb & 15;
        int w13row = gu * 512 + ct * 64 + wq * 16 + cc;
        c.b = g_w13h + ((size_t)e * 1024 + w13row) * HIDDEN + kc0 * 8;
        #pragma unroll
        for (int j = 0; j < 4; j++)
            c.dstB[j] = (uint32_t)(rb * 128 + (((kc0 + j) ^ (rb & 7)) << 4));
    }

    uint32_t arow[4], ar7[4], brow[2], br7[2];
    #pragma unroll
    for (int mi = 0; mi < 4; mi++) {
        uint32_t r = wm * 64 + mi * 16 + (lane & 15);
        arow[mi] = r << 7; ar7[mi] = r & 7;
    }
    #pragma unroll
    for (int q = 0; q < 2; q++) {
        uint32_t r = wn * 32 + q * 16 + (lane & 7) + ((lane >> 4) & 1) * 8;
        brow[q] = r << 7; br7[q] = r & 7;
    }

    float acc[4][4][4];
    #pragma unroll
    for (int i = 0; i < 4; i++)
        #pragma unroll
        for (int j = 0; j < 4; j++)
            #pragma unroll
            for (int q = 0; q < 4; q++) acc[i][j][q] = 0.0f;

    const int NCH = HIDDEN / 64;    // 24
    load_stage(sm, 0, 0, c);  CP_COMMIT();
    load_stage(sm, 1, 64, c); CP_COMMIT();
    for (int k = 0; k < NCH; k++) {
        CP_WAIT1();
        __syncthreads();
        if (k + 2 < NCH) load_stage(sm, (k + 2) % NST, (k + 2) * 64, c);
        CP_COMMIT();
        compute_stage(sm + (k % NST) * STAGE_B, lane, arow, ar7, brow, br7, acc);
    }

    // epilogue: warp's B rows 0..15 = g (ni 0,1), rows 16..31 = u (ni 2,3)
    const int lr = lane >> 2, lc = lane & 3;
    #pragma unroll
    for (int mi = 0; mi < 4; mi++)
        #pragma unroll
        for (int half = 0; half < 2; half++) {
            int row = rt * 256 + wm * 64 + mi * 16 + lr + half * 8;
            if (row >= rows) continue;
            size_t hb = ((size_t)(base + row)) * INTER + ct * 64 + wn * 16 + lc * 2;
            #pragma unroll
            for (int ni = 0; ni < 2; ni++) {
                float g0 = acc[mi][ni][2 * half],     u0 = acc[mi][ni + 2][2 * half];
                float g1 = acc[mi][ni][2 * half + 1], u1 = acc[mi][ni + 2][2 * half + 1];
                float h0 = __fdividef(g0 * u0, 1.0f + __expf(-g0));
                float h1 = __fdividef(g1 * u1, 1.0f + __expf(-g1));
                *(__half2*)(g_h + hb + ni * 8) = __floats2half2_rn(h0, h1);
            }
        }
}

// ---------------- GEMM2 (fp16 HMMA, M=256): y = wt * (h @ W2^T) ----------------
__global__ void __launch_bounds__(512, 1) gemm2_kernel() {
    const int e = blockIdx.z;
    const int rows = g_cnt[e];
    const int rt = blockIdx.x;
    if (rt * 256 >= rows) return;
    const int ct = blockIdx.y;      // 0..11
    const int base = g_off[e];

    extern __shared__ char smraw[];
    uint32_t sm = smem_u32(smraw);
    const int tid = threadIdx.x, wid = tid >> 5, lane = tid & 31;
    const int wm = wid >> 2, wn = wid & 3;

    LoadCtx c;
    {
        int ra = tid >> 1;
        int kc0 = (tid & 1) * 4;
        int arow = rt * 256 + ra;
        int v = arow < rows;
        size_t hrow = (size_t)(base + (v ? arow : 0));
        c.a = g_h + hrow * INTER + kc0 * 8;
        c.asz = v ? 16 : 0;
        #pragma unroll
        for (int j = 0; j < 4; j++)
            c.dstA[j] = (uint32_t)(ra * 128 + (((kc0 + j) ^ (ra & 7)) << 4));

        c.bact = tid < 256;
        int rb = (tid & 255) >> 1;
        size_t brr = (size_t)e * HIDDEN + ct * 128 + rb;
        c.b = g_w2h + brr * INTER + kc0 * 8;
        #pragma unroll
        for (int j = 0; j < 4; j++)
            c.dstB[j] = (uint32_t)(rb * 128 + (((kc0 + j) ^ (rb & 7)) << 4));
    }

    uint32_t arow[4], ar7[4], brow[2], br7[2];
    #pragma unroll
    for (int mi = 0; mi < 4; mi++) {
        uint32_t r = wm * 64 + mi * 16 + (lane & 15);
        arow[mi] = r << 7; ar7[mi] = r & 7;
    }
    #pragma unroll
    for (int q = 0; q < 2; q++) {
        uint32_t r = wn * 32 + q * 16 + (lane & 7) + ((lane >> 4) & 1) * 8;
        brow[q] = r << 7; br7[q] = r & 7;
    }

    float acc[4][4][4];
    #pragma unroll
    for (int i = 0; i < 4; i++)
        #pragma unroll
        for (int j = 0; j < 4; j++)
            #pragma unroll
            for (int q = 0; q < 4; q++) acc[i][j][q] = 0.0f;

    const int NCH = INTER / 64;     // 8
    load_stage(sm, 0, 0, c);  CP_COMMIT();
    load_stage(sm, 1, 64, c); CP_COMMIT();
    for (int k = 0; k < NCH; k++) {
        CP_WAIT1();
        __syncthreads();
        if (k + 2 < NCH) load_stage(sm, (k + 2) % NST, (k + 2) * 64, c);
        CP_COMMIT();
        compute_stage(sm + (k % NST) * STAGE_B, lane, arow, ar7, brow, br7, acc);
    }

    const int lr = lane >> 2, lc = lane & 3;
    #pragma unroll
    for (int mi = 0; mi < 4; mi++)
        #pragma unroll
        for (int half = 0; half < 2; half++) {
            int row = rt * 256 + wm * 64 + mi * 16 + lr + half * 8;
            if (row >= rows) continue;
            float w = g_wt[e * CAP + row];
            __half* yp = g_y + (size_t)(base + row) * HIDDEN + ct * 128 + wn * 32 + lc * 2;
            #pragma unroll
            for (int ni = 0; ni < 4; ni++)
                *(__half2*)(yp + ni * 8) =
                    __floats2half2_rn(w * acc[mi][ni][2 * half], w * acc[mi][ni][2 * half + 1]);
        }
}

// ---------------- gather (2 tokens per 256-thread block) + counter reset ----------------
__global__ void gather_kernel(float* __restrict__ out) {
    const int t = blockIdx.x * 2 + (threadIdx.x >> 7);
    const int lt = threadIdx.x & 127;

    if (blockIdx.x == 0) {
        if (threadIdx.x < NUM_EXPERTS) g_cnt[threadIdx.x] = 0;
        if (threadIdx.x == 0) g_done = 0;
    }

    int rowid[TOP_K];
    #pragma unroll
    for (int k = 0; k < TOP_K; k++) {
        int pp = g_pair[t * TOP_K + k];
        rowid[k] = g_off[pp >> 20] + (pp & 0xFFFFF);
    }
    for (int cc = lt * 8; cc < HIDDEN; cc += 128 * 8) {
        float acc[8] = {};
        #pragma unroll
        for (int k = 0; k < TOP_K; k++) {
            uint4 raw = __ldcs((const uint4*)(g_y + (size_t)rowid[k] * HIDDEN + cc));
            const __half2* hp = (const __half2*)&raw;
            #pragma unroll
            for (int j = 0; j < 4; j++) {
                float2 v = __half22float2(hp[j]);
                acc[2 * j] += v.x; acc[2 * j + 1] += v.y;
            }
        }
        float4* op = (float4*)(out + (size_t)t * HIDDEN + cc);
        op[0] = make_float4(acc[0], acc[1], acc[2], acc[3]);
        op[1] = make_float4(acc[4], acc[5], acc[6], acc[7]);
    }
}

// ---------------- launch ----------------
extern "C" void kernel_launch(void* const* d_in, const int* in_sizes, int n_in,
                              void* d_out, int out_size) {
    const float* x      = (const float*)d_in[0];
    const float* gate_w = (const float*)d_in[1];
    const float* w13    = (const float*)d_in[2];
    const float* w2     = (const float*)d_in[3];
    float* out = (float*)d_out;

    static bool init = false;
    static cudaStream_t s1, s2;
    static cudaEvent_t ev0, ev1, evX, ev2;
    if (!init) {
        cudaStreamCreateWithFlags(&s1, cudaStreamNonBlocking);
        cudaStreamCreateWithFlags(&s2, cudaStreamNonBlocking);
        cudaEventCreateWithFlags(&ev0, cudaEventDisableTiming);
        cudaEventCreateWithFlags(&ev1, cudaEventDisableTiming);
        cudaEventCreateWithFlags(&evX, cudaEventDisableTiming);
        cudaEventCreateWithFlags(&ev2, cudaEventDisableTiming);
        cudaFuncSetAttribute(gemm1_kernel, cudaFuncAttributeMaxDynamicSharedMemorySize, SMEM_DYN);
        cudaFuncSetAttribute(gemm2_kernel, cudaFuncAttributeMaxDynamicSharedMemorySize, SMEM_DYN);
        cudaFuncSetAttribute(router_kernel, cudaFuncAttributeMaxDynamicSharedMemorySize, R_SMEM);
        init = true;
    }

    __half *xh, *w13h, *w2h;
    cudaGetSymbolAddress((void**)&xh,   g_xh);
    cudaGetSymbolAddress((void**)&w13h, g_w13h);
    cudaGetSymbolAddress((void**)&w2h,  g_w2h);

    // fork
    cudaEventRecord(ev0, 0);
    cudaStreamWaitEvent(s1, ev0, 0);
    cudaStreamWaitEvent(s2, ev0, 0);

    // main: router (fused top-8 scatter + fused prefix)
    router_kernel<<<R_BLOCKS, 256, R_SMEM>>>(x, gate_w);

    // s1: w13 conversion ; s2: x conversion (parallel, both needed by gemm1)
    tohalf_kernel<<<4096, 256, 0, s1>>>(w13, w13h, (size_t)NUM_EXPERTS * 2 * INTER * HIDDEN / 8);
    tohalf_kernel<<<2048, 256, 0, s2>>>(x, xh, (size_t)T_TOT * HIDDEN / 8);
    cudaEventRecord(evX, s2);

    // s2 continues with w2 conversion (runs under gemm1)
    tohalf_kernel<<<4096, 256, 0, s2>>>(w2, w2h, (size_t)NUM_EXPERTS * HIDDEN * INTER / 8);
    cudaEventRecord(ev2, s2);

    // gemm1 joins s1 (w13) and evX (x)
    cudaEventRecord(ev1, s1);
    cudaStreamWaitEvent(0, ev1, 0);
    cudaStreamWaitEvent(0, evX, 0);
    gemm1_kernel<<<dim3(T_TOT / 256, INTER / 64, NUM_EXPERTS), 512, SMEM_DYN>>>();

    // gemm2 joins s2 (w2)
    cudaStreamWaitEvent(0, ev2, 0);
    gemm2_kernel<<<dim3(T_TOT / 256, HIDDEN / 128, NUM_EXPERTS), 512, SMEM_DYN>>>();

    gather_kernel<<<T_TOT / 2, 256>>>(out);
}

// round 17
// speedup vs baseline: 1.0418x; 1.0418x over previous
#include <cuda_runtime.h>
#include <cuda_fp16.h>
#include <cstdint>
#include <math.h>

#define NUM_EXPERTS 32
#define TOP_K 8
#define HIDDEN 1536
#define INTER 512
#define T_TOT 8192
#define CAP 8192
#define ROWS_TOT (T_TOT * TOP_K)
#define R_TILE 64
#define R_BLOCKS (T_TOT / R_TILE)   // 128

// ---------------- device scratch (zero-initialized at module load) ----------------
__device__ int   g_cnt[NUM_EXPERTS];
__device__ int   g_off[NUM_EXPERTS];
__device__ int   g_done;
__device__ int   g_tok[NUM_EXPERTS * CAP];
__device__ float g_wt [NUM_EXPERTS * CAP];
__device__ int   g_pair[T_TOT * TOP_K];

__device__ __half g_xh[(size_t)T_TOT * HIDDEN];
__device__ __half g_w13h[(size_t)NUM_EXPERTS * 2 * INTER * HIDDEN];
__device__ __half g_w2h[(size_t)NUM_EXPERTS * HIDDEN * INTER];
__device__ __half g_h[(size_t)ROWS_TOT * INTER];
__device__ __half g_y[(size_t)ROWS_TOT * HIDDEN];

// ---------------- helpers ----------------
__device__ __forceinline__ uint32_t smem_u32(const void* p) {
    uint32_t a;
    asm("{ .reg .u64 t; cvta.to.shared.u64 t, %1; cvt.u32.u64 %0, t; }" : "=r"(a) : "l"(p));
    return a;
}
__device__ __forceinline__ void cp16(uint32_t dst, const void* src, int sz) {
    asm volatile("cp.async.cg.shared.global [%0], [%1], 16, %2;"
                 :: "r"(dst), "l"(__cvta_generic_to_global(src)), "r"(sz));
}
#define CP_COMMIT() asm volatile("cp.async.commit_group;")
#define CP_WAIT1()  asm volatile("cp.async.wait_group 1;")

__device__ __forceinline__ void ldm4(uint32_t* r, uint32_t addr) {
    asm volatile("ldmatrix.sync.aligned.m8n8.x4.shared.b16 {%0,%1,%2,%3}, [%4];"
                 : "=r"(r[0]), "=r"(r[1]), "=r"(r[2]), "=r"(r[3]) : "r"(addr));
}
__device__ __forceinline__ void mma16816(float* c, const uint32_t* a, uint32_t b0, uint32_t b1) {
    asm volatile("mma.sync.aligned.m16n8k16.row.col.f32.f16.f16.f32 "
                 "{%0,%1,%2,%3}, {%4,%5,%6,%7}, {%8,%9}, {%0,%1,%2,%3};"
                 : "+f"(c[0]), "+f"(c[1]), "+f"(c[2]), "+f"(c[3])
                 : "r"(a[0]), "r"(a[1]), "r"(a[2]), "r"(a[3]), "r"(b0), "r"(b1));
}

// smem: 2 tiles (A, B) of 128 rows x 64 fp16 = 128B/row, 16B-chunk XOR swizzle
#define TILE_B  16384
#define OFF_A   0
#define OFF_B   16384
#define STAGE_B 32768
#define NST 3
#define SMEM_DYN (NST * STAGE_B)   // 98304 -> 2 CTAs/SM

struct LoadCtx {
    const __half *a, *b;
    int asz;
    uint32_t dst[4];
};

__device__ __forceinline__ void load_stage(uint32_t sm, int st, int koff, const LoadCtx& c) {
    uint32_t b = sm + st * STAGE_B;
    #pragma unroll
    for (int j = 0; j < 4; j++) {
        cp16(b + OFF_A + c.dst[j], c.a + koff + j * 8, c.asz);
        cp16(b + OFF_B + c.dst[j], c.b + koff + j * 8, 16);
    }
}

__device__ __forceinline__ void compute_stage(
        uint32_t sbase, int lane,
        const uint32_t arow[2], const uint32_t ar7[2],
        const uint32_t brow[4], const uint32_t br7[4],
        float acc[2][8][4]) {
    const uint32_t asel = lane >> 4;
    const uint32_t bsel = (lane >> 3) & 1;
    #pragma unroll
    for (int kk = 0; kk < 4; kk++) {
        uint32_t a[2][4];
        #pragma unroll
        for (int mi = 0; mi < 2; mi++) {
            uint32_t ch = kk * 2 + asel;
            ldm4(a[mi], sbase + OFF_A + arow[mi] + (((ch ^ ar7[mi]) & 7) << 4));
        }
        uint32_t b[4][4];
        #pragma unroll
        for (int q = 0; q < 4; q++) {
            uint32_t ch = kk * 2 + bsel;
            ldm4(b[q], sbase + OFF_B + brow[q] + (((ch ^ br7[q]) & 7) << 4));
        }
        #pragma unroll
        for (int ni = 0; ni < 8; ni++)
            #pragma unroll
            for (int mi = 0; mi < 2; mi++)
                mma16816(acc[mi][ni], a[mi], b[ni >> 1][2 * (ni & 1)], b[ni >> 1][2 * (ni & 1) + 1]);
    }
}

// ---------------- small kernels ----------------
__global__ void tohalf_kernel(const float* __restrict__ src, __half* __restrict__ dst, size_t n8) {
    size_t i = (size_t)blockIdx.x * blockDim.x + threadIdx.x;
    size_t stride = (size_t)gridDim.x * blockDim.x;
    for (; i < n8; i += stride) {
        float4 v0 = __ldcs(((const float4*)src) + 2 * i);
        float4 v1 = __ldcs(((const float4*)src) + 2 * i + 1);
        uint4 o;
        __half2 h0 = __floats2half2_rn(v0.x, v0.y);
        __half2 h1 = __floats2half2_rn(v0.z, v0.w);
        __half2 h2 = __floats2half2_rn(v1.x, v1.y);
        __half2 h3 = __floats2half2_rn(v1.z, v1.w);
        o.x = *(uint32_t*)&h0; o.y = *(uint32_t*)&h1;
        o.z = *(uint32_t*)&h2; o.w = *(uint32_t*)&h3;
        ((uint4*)dst)[i] = o;
    }
}

// ---------------- router: 64-token tiles, logits + fused top-8 + fused prefix ----------------
// Requires g_cnt/g_done == 0 on entry; gather_kernel resets them each invocation.
#define RXS 65
#define RGS 33
#define RLS 33
#define R_SMEM ((128 * RXS + 128 * RGS) * 4)   // 50176 B
__global__ void __launch_bounds__(256) router_kernel(
        const float* __restrict__ x, const float* __restrict__ gate_w) {
    extern __shared__ float rsm[];
    float* xs = rsm;                    // [k*RXS + tok], 64 tokens
    float* gs = rsm + 128 * RXS;        // [k*RGS + e]
    float* ls = rsm;                    // reused: [tok*RLS + e]
    const int tid = threadIdx.x, lane = tid & 31;
    const int t0 = blockIdx.x * R_TILE;
    const int e0 = (tid >> 5) * 4;

    float acc[2][4];
    #pragma unroll
    for (int i = 0; i < 2; i++)
        #pragma unroll
        for (int j = 0; j < 4; j++) acc[i][j] = 0.0f;

    for (int ch = 0; ch < HIDDEN / 128; ch++) {
        __syncthreads();
        // x chunk: 64 tok x 128 k = 2048 float4
        for (int i = tid; i < 2048; i += 256) {
            int tok = i >> 5, kq = i & 31;
            float4 v = *(const float4*)&x[(size_t)(t0 + tok) * HIDDEN + ch * 128 + kq * 4];
            xs[(4 * kq + 0) * RXS + tok] = v.x;
            xs[(4 * kq + 1) * RXS + tok] = v.y;
            xs[(4 * kq + 2) * RXS + tok] = v.z;
            xs[(4 * kq + 3) * RXS + tok] = v.w;
        }
        // gate chunk: 32 e x 128 k = 1024 float4
        for (int i = tid; i < 1024; i += 256) {
            int e = i >> 5, kq = i & 31;
            float4 v = *(const float4*)&gate_w[(size_t)e * HIDDEN + ch * 128 + kq * 4];
            gs[(4 * kq + 0) * RGS + e] = v.x;
            gs[(4 * kq + 1) * RGS + e] = v.y;
            gs[(4 * kq + 2) * RGS + e] = v.z;
            gs[(4 * kq + 3) * RGS + e] = v.w;
        }
        __syncthreads();
        #pragma unroll 4
        for (int kk = 0; kk < 128; kk++) {
            float gg[4];
            #pragma unroll
            for (int j = 0; j < 4; j++) gg[j] = gs[kk * RGS + e0 + j];
            #pragma unroll
            for (int i = 0; i < 2; i++) {
                float xv = xs[kk * RXS + lane + 32 * i];
                #pragma unroll
                for (int j = 0; j < 4; j++) acc[i][j] = fmaf(xv, gg[j], acc[i][j]);
            }
        }
    }

    __syncthreads();
    #pragma unroll
    for (int i = 0; i < 2; i++)
        #pragma unroll
        for (int j = 0; j < 4; j++)
            ls[(lane + 32 * i) * RLS + e0 + j] = acc[i][j];
    __syncthreads();

    if (tid < R_TILE) {
        const int t = t0 + tid;
        float lg[NUM_EXPERTS];
        #pragma unroll
        for (int i = 0; i < NUM_EXPERTS; i++) lg[i] = ls[tid * RLS + i];
        float mx = -INFINITY;
        #pragma unroll
        for (int i = 0; i < NUM_EXPERTS; i++) mx = fmaxf(mx, lg[i]);
        float pr[NUM_EXPERTS];
        #pragma unroll
        for (int i = 0; i < NUM_EXPERTS; i++) pr[i] = expf(lg[i] - mx);
        int idx[TOP_K]; float w[TOP_K]; float ws = 0.0f;
        unsigned used = 0u;
        #pragma unroll
        for (int k = 0; k < TOP_K; k++) {
            int bi = -1; float bv = -INFINITY;
            #pragma unroll
            for (int i = 0; i < NUM_EXPERTS; i++)
                if (!(used >> i & 1u) && pr[i] > bv) { bv = pr[i]; bi = i; }
            used |= 1u << bi; idx[k] = bi; w[k] = bv; ws += bv;
        }
        float inv = 1.0f / ws;
        #pragma unroll
        for (int k = 0; k < TOP_K; k++) {
            int slot = atomicAdd(&g_cnt[idx[k]], 1);
            g_tok[idx[k] * CAP + slot] = t;
            g_wt [idx[k] * CAP + slot] = w[k] * inv;
            g_pair[t * TOP_K + k] = (idx[k] << 20) | slot;
        }
    }

    // fused prefix: last block to finish computes g_off
    __syncthreads();
    if (tid == 0) {
        __threadfence();
        int old = atomicAdd(&g_done, 1);
        if (old == R_BLOCKS - 1) {
            int s = 0;
            for (int e = 0; e < NUM_EXPERTS; e++) { g_off[e] = s; s += g_cnt[e]; }
        }
    }
}

// ---------------- GEMM1 (fp16 HMMA): gu = X @ W13^T, h = silu(g)*u -> g_h ----------------
__global__ void __launch_bounds__(256, 2) gemm1_kernel() {
    const int e = blockIdx.z;
    const int rows = g_cnt[e];
    const int rt = blockIdx.x;
    if (rt * 128 >= rows) return;
    const int ct = blockIdx.y;
    const int base = g_off[e];

    extern __shared__ char smraw[];
    uint32_t sm = smem_u32(smraw);
    const int tid = threadIdx.x, wid = tid >> 5, lane = tid & 31;
    const int wm = wid >> 1, wn = wid & 1;

    LoadCtx c;
    {
        int r = tid >> 1;
        int kc0 = (tid & 1) * 4;
        int arow = rt * 128 + r;
        int v = arow < rows;
        int tok = v ? g_tok[e * CAP + arow] : 0;
        c.a = g_xh + (size_t)tok * HIDDEN + kc0 * 8;
        c.asz = v ? 16 : 0;
        int half = (r >> 5) & 1, wnn = r >> 6, cc = r & 31;
        int w13row = half * 512 + ct * 64 + wnn * 32 + cc;
        c.b = g_w13h + ((size_t)e * 1024 + w13row) * HIDDEN + kc0 * 8;
        #pragma unroll
        for (int j = 0; j < 4; j++)
            c.dst[j] = (uint32_t)(r * 128 + (((kc0 + j) ^ (r & 7)) << 4));
    }

    uint32_t arow[2], ar7[2], brow[4], br7[4];
    #pragma unroll
    for (int mi = 0; mi < 2; mi++) {
        uint32_t r = wm * 32 + mi * 16 + (lane & 15);
        arow[mi] = r << 7; ar7[mi] = r & 7;
    }
    #pragma unroll
    for (int q = 0; q < 4; q++) {
        uint32_t r = wn * 64 + q * 16 + (lane & 7) + ((lane >> 4) & 1) * 8;
        brow[q] = r << 7; br7[q] = r & 7;
    }

    float acc[2][8][4];
    #pragma unroll
    for (int i = 0; i < 2; i++)
        #pragma unroll
        for (int j = 0; j < 8; j++)
            #pragma unroll
            for (int q = 0; q < 4; q++) acc[i][j][q] = 0.0f;

    const int NCH = HIDDEN / 64;
    load_stage(sm, 0, 0, c);  CP_COMMIT();
    load_stage(sm, 1, 64, c); CP_COMMIT();
    for (int k = 0; k < NCH; k++) {
        CP_WAIT1();
        __syncthreads();
        if (k + 2 < NCH) load_stage(sm, (k + 2) % NST, (k + 2) * 64, c);
        CP_COMMIT();
        compute_stage(sm + (k % NST) * STAGE_B, lane, arow, ar7, brow, br7, acc);
    }

    const int lr = lane >> 2, lc = lane & 3;
    #pragma unroll
    for (int mi = 0; mi < 2; mi++)
        #pragma unroll
        for (int half = 0; half < 2; half++) {
            int row = rt * 128 + wm * 32 + mi * 16 + lr + half * 8;
            if (row >= rows) continue;
            size_t hb = ((size_t)(base + row)) * INTER + ct * 64 + wn * 32 + lc * 2;
            #pragma unroll
            for (int ni = 0; ni < 4; ni++) {
                float g0 = acc[mi][ni][2 * half],     u0 = acc[mi][ni + 4][2 * half];
                float g1 = acc[mi][ni][2 * half + 1], u1 = acc[mi][ni + 4][2 * half + 1];
                float h0 = __fdividef(g0 * u0, 1.0f + __expf(-g0));
                float h1 = __fdividef(g1 * u1, 1.0f + __expf(-g1));
                *(__half2*)(g_h + hb + ni * 8) = __floats2half2_rn(h0, h1);
            }
        }
}

// ---------------- GEMM2 (fp16 HMMA): y = wt * (h @ W2^T) -> fp16 ----------------
__global__ void __launch_bounds__(256, 2) gemm2_kernel() {
    const int e = blockIdx.z;
    const int rows = g_cnt[e];
    const int rt = blockIdx.x;
    if (rt * 128 >= rows) return;
    const int ct = blockIdx.y;
    const int base = g_off[e];

    extern __shared__ char smraw[];
    uint32_t sm = smem_u32(smraw);
    const int tid = threadIdx.x, wid = tid >> 5, lane = tid & 31;
    const int wm = wid >> 1, wn = wid & 1;

    LoadCtx c;
    {
        int r = tid >> 1;
        int kc0 = (tid & 1) * 4;
        int arow = rt * 128 + r;
        int v = arow < rows;
        size_t hrow = (size_t)(base + (v ? arow : 0));
        c.a = g_h + hrow * INTER + kc0 * 8;
        c.asz = v ? 16 : 0;
        size_t brr = (size_t)e * HIDDEN + ct * 128 + r;
        c.b = g_w2h + brr * INTER + kc0 * 8;
        #pragma unroll
        for (int j = 0; j < 4; j++)
            c.dst[j] = (uint32_t)(r * 128 + (((kc0 + j) ^ (r & 7)) << 4));
    }

    uint32_t arow[2], ar7[2], brow[4], br7[4];
    #pragma unroll
    for (int mi = 0; mi < 2; mi++) {
        uint32_t r = wm * 32 + mi * 16 + (lane & 15);
        arow[mi] = r << 7; ar7[mi] = r & 7;
    }
    #pragma unroll
    for (int q = 0; q < 4; q++) {
        uint32_t r = wn * 64 + q * 16 + (lane & 7) + ((lane >> 4) & 1) * 8;
        brow[q] = r << 7; br7[q] = r & 7;
    }

    float acc[2][8][4];
    #pragma unroll
    for (int i = 0; i < 2; i++)
        #pragma unroll
        for (int j = 0; j < 8; j++)
            #pragma unroll
            for (int q = 0; q < 4; q++) acc[i][j][q] = 0.0f;

    const int NCH = INTER / 64;
    load_stage(sm, 0, 0, c);  CP_COMMIT();
    load_stage(sm, 1, 64, c); CP_COMMIT();
    for (int k = 0; k < NCH; k++) {
        CP_WAIT1();
        __syncthreads();
        if (k + 2 < NCH) load_stage(sm, (k + 2) % NST, (k + 2) * 64, c);
        CP_COMMIT();
        compute_stage(sm + (k % NST) * STAGE_B, lane, arow, ar7, brow, br7, acc);
    }

    const int lr = lane >> 2, lc = lane & 3;
    #pragma unroll
    for (int mi = 0; mi < 2; mi++)
        #pragma unroll
        for (int half = 0; half < 2; half++) {
            int row = rt * 128 + wm * 32 + mi * 16 + lr + half * 8;
            if (row >= rows) continue;
            float w = g_wt[e * CAP + row];
            __half* yp = g_y + (size_t)(base + row) * HIDDEN + ct * 128 + wn * 64 + lc * 2;
            #pragma unroll
            for (int ni = 0; ni < 8; ni++)
                *(__half2*)(yp + ni * 8) =
                    __floats2half2_rn(w * acc[mi][ni][2 * half], w * acc[mi][ni][2 * half + 1]);
        }
}

// ---------------- gather (2 tokens per 256-thread block) + counter reset ----------------
__global__ void gather_kernel(float* __restrict__ out) {
    const int t = blockIdx.x * 2 + (threadIdx.x >> 7);
    const int lt = threadIdx.x & 127;

    if (blockIdx.x == 0) {
        if (threadIdx.x < NUM_EXPERTS) g_cnt[threadIdx.x] = 0;
        if (threadIdx.x == 0) g_done = 0;
    }

    int rowid[TOP_K];
    #pragma unroll
    for (int k = 0; k < TOP_K; k++) {
        int pp = g_pair[t * TOP_K + k];
        rowid[k] = g_off[pp >> 20] + (pp & 0xFFFFF);
    }
    for (int cc = lt * 8; cc < HIDDEN; cc += 128 * 8) {
        float acc[8] = {};
        #pragma unroll
        for (int k = 0; k < TOP_K; k++) {
            uint4 raw = __ldcs((const uint4*)(g_y + (size_t)rowid[k] * HIDDEN + cc));
            const __half2* hp = (const __half2*)&raw;
            #pragma unroll
            for (int j = 0; j < 4; j++) {
                float2 v = __half22float2(hp[j]);
                acc[2 * j] += v.x; acc[2 * j + 1] += v.y;
            }
        }
        float4* op = (float4*)(out + (size_t)t * HIDDEN + cc);
        op[0] = make_float4(acc[0], acc[1], acc[2], acc[3]);
        op[1] = make_float4(acc[4], acc[5], acc[6], acc[7]);
    }
}

// ---------------- launch ----------------
extern "C" void kernel_launch(void* const* d_in, const int* in_sizes, int n_in,
                              void* d_out, int out_size) {
    const float* x      = (const float*)d_in[0];
    const float* gate_w = (const float*)d_in[1];
    const float* w13    = (const float*)d_in[2];
    const float* w2     = (const float*)d_in[3];
    float* out = (float*)d_out;

    static bool init = false;
    static cudaStream_t s1, s2;
    static cudaEvent_t ev0, ev1, evX, ev2;
    if (!init) {
        cudaStreamCreateWithFlags(&s1, cudaStreamNonBlocking);
        cudaStreamCreateWithFlags(&s2, cudaStreamNonBlocking);
        cudaEventCreateWithFlags(&ev0, cudaEventDisableTiming);
        cudaEventCreateWithFlags(&ev1, cudaEventDisableTiming);
        cudaEventCreateWithFlags(&evX, cudaEventDisableTiming);
        cudaEventCreateWithFlags(&ev2, cudaEventDisableTiming);
        cudaFuncSetAttribute(gemm1_kernel, cudaFuncAttributeMaxDynamicSharedMemorySize, SMEM_DYN);
        cudaFuncSetAttribute(gemm2_kernel, cudaFuncAttributeMaxDynamicSharedMemorySize, SMEM_DYN);
        cudaFuncSetAttribute(router_kernel, cudaFuncAttributeMaxDynamicSharedMemorySize, R_SMEM);
        init = true;
    }

    __half *xh, *w13h, *w2h;
    cudaGetSymbolAddress((void**)&xh,   g_xh);
    cudaGetSymbolAddress((void**)&w13h, g_w13h);
    cudaGetSymbolAddress((void**)&w2h,  g_w2h);

    // fork
    cudaEventRecord(ev0, 0);
    cudaStreamWaitEvent(s1, ev0, 0);
    cudaStreamWaitEvent(s2, ev0, 0);

    // main: router (128 blocks, fused top-8 scatter + fused prefix)
    router_kernel<<<R_BLOCKS, 256, R_SMEM>>>(x, gate_w);

    // s1: w13 conversion ; s2: x conversion (parallel, both needed by gemm1)
    tohalf_kernel<<<4096, 256, 0, s1>>>(w13, w13h, (size_t)NUM_EXPERTS * 2 * INTER * HIDDEN / 8);
    tohalf_kernel<<<2048, 256, 0, s2>>>(x, xh, (size_t)T_TOT * HIDDEN / 8);
    cudaEventRecord(evX, s2);

    // s2 continues with w2 conversion (runs under gemm1)
    tohalf_kernel<<<4096, 256, 0, s2>>>(w2, w2h, (size_t)NUM_EXPERTS * HIDDEN * INTER / 8);
    cudaEventRecord(ev2, s2);

    // gemm1 joins s1 (w13) and evX (x)
    cudaEventRecord(ev1, s1);
    cudaStreamWaitEvent(0, ev1, 0);
    cudaStreamWaitEvent(0, evX, 0);
    gemm1_kernel<<<dim3(T_TOT / 128, INTER / 64, NUM_EXPERTS), 256, SMEM_DYN>>>();

    // gemm2 joins s2 (w2)
    cudaStreamWaitEvent(0, ev2, 0);
    gemm2_kernel<<<dim3(T_TOT / 128, HIDDEN / 128, NUM_EXPERTS), 256, SMEM_DYN>>>();

    gather_kernel<<<T_TOT / 2, 256>>>(out);
}